// round 16
// baseline (speedup 1.0000x reference)
#include <cuda_runtime.h>

#define PITCH 68
#define NB (64 * PITCH)

// ---- compile-time Dirichlet taps (folded to FFMA immediates) ----
struct Gtab { float v[64]; };

__host__ __device__ constexpr double csin(double x) {
    double t = x, s = x, x2 = x * x;
    for (int n = 1; n < 16; n++) { t *= -x2 / (double)((2 * n) * (2 * n + 1)); s += t; }
    return s;
}
__host__ __device__ constexpr float gof(int t) {   // g(t), t in [0,63], 64-periodic
    int m = 2 * t + 1;
    int r1 = (63 * m) % 256; if (r1 >= 128) r1 -= 256;
    int r2 = m % 256;        if (r2 >= 128) r2 -= 256;
    const double PI = 3.14159265358979323846;
    return (float)(csin(PI * r1 / 128.0) / csin(PI * r2 / 128.0) / 64.0);
}
__host__ __device__ constexpr Gtab make_g(int SH) {
    Gtab G{};
    for (int d = 0; d < 64; d++) G.v[d] = gof(((d - SH) % 64 + 64) % 64);
    return G;
}

// Left circulant as conv: dst[i][j] = sum_d g(d-SH) * src[(i-d)&63][j].
// 8 rows x 4 cols per thread; shift-window of 8 float4 (register-renamed, MOV-free).
template<int SH>
__device__ __forceinline__ void conv_left(float acc[8][4], const float* __restrict__ src,
                                          int r0, int c0) {
    constexpr Gtab GT = make_g(SH);
    #pragma unroll
    for (int r = 0; r < 8; r++)
        #pragma unroll
        for (int q = 0; q < 4; q++) acc[r][q] = 0.f;
    float4 W[8];
    #pragma unroll
    for (int j = 0; j < 8; j++)
        W[j] = *(const float4*)&src[((r0 + j) & 63) * PITCH + c0];
    #pragma unroll
    for (int d = 0; d < 64; d++) {
        const float g = GT.v[d];
        #pragma unroll
        for (int r = 0; r < 8; r++) {
            acc[r][0] = fmaf(g, W[r].x, acc[r][0]);
            acc[r][1] = fmaf(g, W[r].y, acc[r][1]);
            acc[r][2] = fmaf(g, W[r].z, acc[r][2]);
            acc[r][3] = fmaf(g, W[r].w, acc[r][3]);
        }
        if (d < 63) {
            #pragma unroll
            for (int j = 7; j > 0; j--) W[j] = W[j - 1];
            W[0] = *(const float4*)&src[((r0 - d - 1) & 63) * PITCH + c0];
        }
    }
}

// Right circulant^T as conv: dst[i][m] = sum_d g(d-SH) * src[i][(m-d)&63].
// Two half-passes of 4 rows to bound registers; P/Q sliding float4 windows.
template<int SH>
__device__ __forceinline__ void conv_right(float acc[8][4], const float* __restrict__ src,
                                           int r0, int c0) {
    constexpr Gtab GT = make_g(SH);
    #pragma unroll
    for (int r = 0; r < 8; r++)
        #pragma unroll
        for (int q = 0; q < 4; q++) acc[r][q] = 0.f;
    #pragma unroll
    for (int h = 0; h < 2; h++) {
        float4 P[4], Q[4];
        #pragma unroll
        for (int r = 0; r < 4; r++)
            P[r] = *(const float4*)&src[(r0 + 4 * h + r) * PITCH + c0];
        #pragma unroll
        for (int a = 0; a < 16; a++) {
            const int qc = (c0 - 4 * a - 4) & 63;
            #pragma unroll
            for (int r = 0; r < 4; r++)
                Q[r] = *(const float4*)&src[(r0 + 4 * h + r) * PITCH + qc];
            #pragma unroll
            for (int b = 0; b < 4; b++) {
                const float g = GT.v[4 * a + b];
                #pragma unroll
                for (int r = 0; r < 4; r++) {
                    const float* Pf = (const float*)&P[r];
                    const float* Qf = (const float*)&Q[r];
                    #pragma unroll
                    for (int q = 0; q < 4; q++) {
                        float s = (q >= b) ? Pf[q - b] : Qf[q - b + 4];
                        acc[4 * h + r][q] = fmaf(g, s, acc[4 * h + r][q]);
                    }
                }
            }
            #pragma unroll
            for (int r = 0; r < 4; r++) P[r] = Q[r];
        }
    }
}

__device__ __forceinline__ void store8(float* __restrict__ dst, float acc[8][4],
                                       int r0, int c0) {
    #pragma unroll
    for (int r = 0; r < 8; r++)
        *(float4*)&dst[(r0 + r) * PITCH + c0] =
            make_float4(acc[r][0], acc[r][1], acc[r][2], acc[r][3]);
}

__global__ void __launch_bounds__(128, 3)
uppolyact_kernel(const float* __restrict__ xg,
                 const float* __restrict__ coef,
                 float* __restrict__ outg) {
    extern __shared__ float sm[];
    float* B0 = sm;            // x -> oo^2
    float* B1 = sm + NB;       // Gx -> oe^2 -> tmp
    float* B2 = sm + 2 * NB;   // xG^T -> eo^2
    float* Pr  = sm + 3 * NB;  // 8 x 68
    float* Pc  = Pr + 544;     // 16 x 68
    float* rs  = Pc + 1088;    // 64
    float* cs  = rs + 64;      // 64
    float* rs1 = cs + 64;      // 64
    float* cs2 = rs1 + 64;     // 64
    float* tsp = cs2 + 64;     // 1

    const int tid = threadIdx.x;
    const int rg = tid >> 4, cg = tid & 15;
    const int r0 = rg << 3, c0 = cg << 2;
    const float* xin = xg + (size_t)blockIdx.x * 4096;
    float* outp = outg + (size_t)blockIdx.x * 4096;
    const float inv64 = 1.0f / 64.0f;

    const float k0 = __ldg(&coef[0]), k1 = __ldg(&coef[1]);
    const float k2q = 0.25f * __ldg(&coef[2]);

    // ---- P0: load image; x rank-1 partials ----
    {
        float4 xv[8];
        #pragma unroll
        for (int r = 0; r < 8; r++) {
            xv[r] = *(const float4*)&xin[(r0 + r) * 64 + c0];
            *(float4*)&B0[(r0 + r) * PITCH + c0] = xv[r];
        }
        float4 pr = make_float4(0.f, 0.f, 0.f, 0.f);
        #pragma unroll
        for (int r = 0; r < 8; r++) {
            float sg = (r & 1) ? -1.f : 1.f;
            pr.x += sg * xv[r].x; pr.y += sg * xv[r].y;
            pr.z += sg * xv[r].z; pr.w += sg * xv[r].w;
        }
        *(float4*)&Pr[rg * 68 + c0] = pr;
        float pc[8];
        #pragma unroll
        for (int r = 0; r < 8; r++)
            pc[r] = xv[r].x - xv[r].y + xv[r].z - xv[r].w;
        *(float4*)&Pc[cg * 68 + r0]     = make_float4(pc[0], pc[1], pc[2], pc[3]);
        *(float4*)&Pc[cg * 68 + r0 + 4] = make_float4(pc[4], pc[5], pc[6], pc[7]);
    }
    __syncthreads();

    // ---- P1: rs/cs reduce + a1 = Gx ; a2 = xG^T ----
    if (tid < 64) {
        float s = 0.f, t = 0.f;
        #pragma unroll
        for (int g = 0; g < 8; g++)  s += Pr[g * 68 + tid];
        #pragma unroll
        for (int g = 0; g < 16; g++) t += Pc[g * 68 + tid];
        rs[tid] = s; cs[tid] = t;
    }
    {
        float a1[8][4];
        conv_left<0>(a1, B0, r0, c0);
        store8(B1, a1, r0, c0);
        float pc[8];
        #pragma unroll
        for (int r = 0; r < 8; r++)
            pc[r] = a1[r][0] - a1[r][1] + a1[r][2] - a1[r][3];
        *(float4*)&Pc[cg * 68 + r0]     = make_float4(pc[0], pc[1], pc[2], pc[3]);
        *(float4*)&Pc[cg * 68 + r0 + 4] = make_float4(pc[4], pc[5], pc[6], pc[7]);
    }
    {
        float a2[8][4];
        conv_right<0>(a2, B0, r0, c0);
        store8(B2, a2, r0, c0);
        float4 pr = make_float4(0.f, 0.f, 0.f, 0.f);
        #pragma unroll
        for (int r = 0; r < 8; r++) {
            float sg = (r & 1) ? -1.f : 1.f;
            pr.x += sg * a2[r][0]; pr.y += sg * a2[r][1];
            pr.z += sg * a2[r][2]; pr.w += sg * a2[r][3];
        }
        *(float4*)&Pr[rg * 68 + c0] = pr;
    }
    __syncthreads();

    // ---- P2a: rs1/cs2/ts reduces + a3 = (Gx)G^T ----
    if (tid < 64) {
        float s = 0.f, t = 0.f;
        #pragma unroll
        for (int g = 0; g < 8; g++)  s += Pr[g * 68 + tid];
        #pragma unroll
        for (int g = 0; g < 16; g++) t += Pc[g * 68 + tid];
        rs1[tid] = s; cs2[tid] = t;
    } else if (tid < 96) {
        int l = tid - 64;
        float v = rs[2 * l] - rs[2 * l + 1];
        #pragma unroll
        for (int o = 16; o > 0; o >>= 1) v += __shfl_xor_sync(~0u, v, o);
        if (l == 0) tsp[0] = v;
    }
    float a3[8][4];
    conv_right<0>(a3, B1, r0, c0);
    __syncthreads();

    // ---- P2b: corrections + squares: B0<-oo^2 B1<-oe^2 B2<-eo^2 ----
    {
        float4 rv1 = *(const float4*)&rs1[c0];
        #pragma unroll
        for (int r = 0; r < 8; r++) {
            int i = r0 + r;
            float sgni = (i & 1) ? -1.f : 1.f;
            float cs2v = cs2[i] * inv64;
            int base = i * PITCH + c0;
            float4 v1 = *(float4*)&B1[base];
            float4 v2 = *(float4*)&B2[base];
            float4 eo, oe, oo;
            eo.x = v2.x + sgni * rv1.x * inv64;
            eo.y = v2.y + sgni * rv1.y * inv64;
            eo.z = v2.z + sgni * rv1.z * inv64;
            eo.w = v2.w + sgni * rv1.w * inv64;
            oe.x = v1.x + cs2v;  oe.y = v1.y - cs2v;
            oe.z = v1.z + cs2v;  oe.w = v1.w - cs2v;
            oo.x = a3[r][0]; oo.y = a3[r][1]; oo.z = a3[r][2]; oo.w = a3[r][3];
            eo.x *= eo.x; eo.y *= eo.y; eo.z *= eo.z; eo.w *= eo.w;
            oe.x *= oe.x; oe.y *= oe.y; oe.z *= oe.z; oe.w *= oe.w;
            oo.x *= oo.x; oo.y *= oo.y; oo.z *= oo.z; oo.w *= oo.w;
            *(float4*)&B2[base] = eo;
            *(float4*)&B1[base] = oe;
            *(float4*)&B0[base] = oo;
        }
    }
    __syncthreads();

    // ---- P3: tmp: B1 = oe^2 + oo^2 G'^T ----
    {
        float acc[8][4];
        conv_right<1>(acc, B0, r0, c0);
        #pragma unroll
        for (int r = 0; r < 8; r++) {
            int base = (r0 + r) * PITCH + c0;
            float4 d = *(float4*)&B1[base];
            d.x += acc[r][0]; d.y += acc[r][1]; d.z += acc[r][2]; d.w += acc[r][3];
            *(float4*)&B1[base] = d;
        }
    }
    __syncthreads();

    // ---- P4: F = G'*tmp ; E = eo^2 G'^T ; final combine ----
    {
        float Fa[8][4];
        conv_left<1>(Fa, B1, r0, c0);
        float Ea[8][4];
        conv_right<1>(Ea, B2, r0, c0);
        const float ts = tsp[0];
        const float inv4096 = inv64 * inv64;
        float4 rv = *(const float4*)&rs[c0];
        #pragma unroll
        for (int r = 0; r < 8; r++) {
            int i = r0 + r;
            float sgni = (i & 1) ? -1.f : 1.f;
            float4 xv = *(const float4*)&xin[i * 64 + c0];
            float csv = cs[i] * inv64;
            float tci = sgni * ts * inv4096;
            float vx = xv.x + sgni * rv.x * inv64 + csv + tci;
            float vy = xv.y + sgni * rv.y * inv64 - csv - tci;
            float vz = xv.z + sgni * rv.z * inv64 + csv + tci;
            float vw = xv.w + sgni * rv.w * inv64 - csv - tci;
            float4 o;
            o.x = k0 + k1 * xv.x + k2q * (vx * vx + Ea[r][0] + Fa[r][0]);
            o.y = k0 + k1 * xv.y + k2q * (vy * vy + Ea[r][1] + Fa[r][1]);
            o.z = k0 + k1 * xv.z + k2q * (vz * vz + Ea[r][2] + Fa[r][2]);
            o.w = k0 + k1 * xv.w + k2q * (vw * vw + Ea[r][3] + Fa[r][3]);
            *(float4*)&outp[i * 64 + c0] = o;
        }
    }
}

extern "C" void kernel_launch(void* const* d_in, const int* in_sizes, int n_in,
                              void* d_out, int out_size) {
    const float* x    = (const float*)d_in[0];
    const float* coef = (const float*)d_in[1];
    float* out = (float*)d_out;

    int smem_bytes = 3 * NB * (int)sizeof(float)
                   + (544 + 1088 + 4 * 64 + 4) * (int)sizeof(float);   // ~59.8 KB
    cudaFuncSetAttribute(uppolyact_kernel,
                         cudaFuncAttributeMaxDynamicSharedMemorySize, smem_bytes);

    int nimg = in_sizes[0] / 4096;   // 4096 images of 64x64
    uppolyact_kernel<<<nimg, 128, smem_bytes>>>(x, coef, out);
}